// round 5
// baseline (speedup 1.0000x reference)
#include <cuda_runtime.h>
#include <cuda_bf16.h>
#include <math.h>

#define EPSF 1e-6f
#define BATCH 128
#define TLEN  2048
#define CH    128
#define EDIM  32
#define HDIM  64
#define PRED  336

// scratch (allocation-free rule: __device__ globals)
__device__ __align__(16) float g_v[BATCH * EDIM];              // 16 KB
__device__ __align__(16) float g_tvn[PRED * BATCH * EDIM];     // 5.5 MB

// ---------------------------------------------------------------------------
// Kernel A: per-row moving-average decomposition + 4 GEMVs + tanh -> v[128,32]
// ---------------------------------------------------------------------------
__global__ void __launch_bounds__(256) ka_encoder(
    const float* __restrict__ x,
    const float* __restrict__ Wt, const float* __restrict__ bt,
    const float* __restrict__ Ww, const float* __restrict__ bw,
    const float* __restrict__ Wdm, const float* __restrict__ bdm,
    const float* __restrict__ Wre, const float* __restrict__ bre)
{
    int b = blockIdx.x;
    int tid = threadIdx.x;
    __shared__ float s0[TLEN];   // x[:,:,0] then residual
    __shared__ float st[TLEN];   // trend
    __shared__ float part[256];
    __shared__ float acc4[4][EDIM];

    const float* xb = x + (size_t)b * TLEN * CH;
    for (int t = tid; t < TLEN; t += 256) s0[t] = xb[(size_t)t * CH];
    __syncthreads();
    for (int t = tid; t < TLEN; t += 256) {
        float s = 0.f;
        #pragma unroll
        for (int d = -3; d <= 3; d++) {
            int u = t + d; u = min(max(u, 0), TLEN - 1);
            s += s0[u];
        }
        st[t] = s / 7.0f;
    }
    __syncthreads();
    for (int t = tid; t < TLEN; t += 256) s0[t] = s0[t] - st[t]; // residual
    __syncthreads();

    int combo = tid & 127;
    int e = combo & 31;
    int m = combo >> 5;         // 0: trend, 1: weekly, 2: daily, 3: resid
    int half = tid >> 7;
    const float* W = (m == 0) ? Wt : (m == 1) ? Ww : (m == 2) ? Wdm : Wre;
    const float* sig = (m == 0) ? st : s0;
    float a = 0.f;
    int tbeg = half * (TLEN / 2);
    #pragma unroll 4
    for (int t = tbeg; t < tbeg + TLEN / 2; t++)
        a = fmaf(sig[t], W[t * EDIM + e], a);
    part[tid] = a;
    __syncthreads();
    if (tid < 128) {
        float d = part[tid] + part[tid + 128];
        const float* be = (m == 0) ? bt : (m == 1) ? bw : (m == 2) ? bdm : bre;
        acc4[m][e] = tanhf(d + be[e]);
    }
    __syncthreads();
    if (tid < EDIM)
        g_v[b * EDIM + tid] = ((acc4[0][tid] + acc4[1][tid]) + acc4[2][tid]) + acc4[3][tid];
}

// ---------------------------------------------------------------------------
// Kernel B: 336-step serial scan, one 64-thread block per batch row.
// State (32-vector) replicated in every thread's registers; norms are local.
// Stores tv_{s+1} (= logmap0(expmap0(vn_s))) to g_tvn; Wr projection deferred.
// ---------------------------------------------------------------------------
#define DO_MAP()                                                               \
    {                                                                          \
        float a0 = 0.f, a1 = 0.f, a2 = 0.f, a3 = 0.f;                          \
        _Pragma("unroll")                                                      \
        for (int k = 0; k < 8; k++) {                                          \
            a0 = fmaf(vn[4*k+0], vn[4*k+0], a0);                               \
            a1 = fmaf(vn[4*k+1], vn[4*k+1], a1);                               \
            a2 = fmaf(vn[4*k+2], vn[4*k+2], a2);                               \
            a3 = fmaf(vn[4*k+3], vn[4*k+3], a3);                               \
        }                                                                      \
        float r = sqrtf((a0 + a1) + (a2 + a3));                                \
        float x0 = coshf(r);                                                   \
        float scale = (r > EPSF) ? (sinhf(r) / fmaxf(r, EPSF)) : 1.0f;         \
        float r2 = acoshf(fmaxf(x0, 1.0f));                                    \
        float b0 = 0.f, b1 = 0.f, b2 = 0.f, b3 = 0.f;                          \
        _Pragma("unroll")                                                      \
        for (int k = 0; k < 8; k++) {                                          \
            float x0v = scale * vn[4*k+0];                                     \
            float x1v = scale * vn[4*k+1];                                     \
            float x2v = scale * vn[4*k+2];                                     \
            float x3v = scale * vn[4*k+3];                                     \
            b0 = fmaf(x0v, x0v, b0);                                           \
            b1 = fmaf(x1v, x1v, b1);                                           \
            b2 = fmaf(x2v, x2v, b2);                                           \
            b3 = fmaf(x3v, x3v, b3);                                           \
        }                                                                      \
        float nn = sqrtf((b0 + b1) + (b2 + b3));                               \
        float cm = r2 / fmaxf(nn, EPSF);                                       \
        _Pragma("unroll")                                                      \
        for (int i = 0; i < 32; i++) tv[i] = cm * (scale * vn[i]);             \
    }

__global__ void __launch_bounds__(64) kb_scan(
    const float* __restrict__ Wd_in, const float* __restrict__ bd_in,
    const float* __restrict__ Wd_gate, const float* __restrict__ bd_gate,
    const float* __restrict__ Wd_out, const float* __restrict__ bd_out)
{
    int b = blockIdx.x;
    int t = threadIdx.x;
    int lane = t & 31;
    int w = t >> 5;

    // padded shared layouts (row stride 68 floats = 272B -> conflict-free LDS.128)
    __shared__ __align__(16) float sWhg[64 * 68]; // [h-col t][pair(Win, Wgate) over i]
    __shared__ __align__(16) float sWo[32 * 68];  // [e-row i][j over 64]
    __shared__ __align__(16) float sU[64];
    __shared__ __align__(16) float sP[64];        // two wv partials

    for (int idx = t; idx < EDIM * HDIM; idx += 64) {
        int i = idx >> 6, c = idx & 63;          // Wd_in[i][c], i<32, c<64
        sWhg[c * 68 + 2 * i]     = Wd_in[idx];
        sWhg[c * 68 + 2 * i + 1] = Wd_gate[idx];
    }
    for (int idx = t; idx < HDIM * EDIM; idx += 64) {
        int j = idx >> 5, i = idx & 31;          // Wd_out[j][i]
        sWo[i * 68 + j] = Wd_out[idx];
    }
    float hb = bd_in[t];
    float gb = bd_gate[t];

    float bdoV[32];
    {
        const float4* bp = (const float4*)bd_out;
        #pragma unroll
        for (int k = 0; k < 8; k++) {
            float4 f = bp[k];
            bdoV[4*k] = f.x; bdoV[4*k+1] = f.y; bdoV[4*k+2] = f.z; bdoV[4*k+3] = f.w;
        }
    }
    float vn[32], tv[32];
    {
        const float4* vp = (const float4*)(g_v + b * EDIM);
        #pragma unroll
        for (int k = 0; k < 8; k++) {
            float4 f = vp[k];
            vn[4*k] = f.x; vn[4*k+1] = f.y; vn[4*k+2] = f.z; vn[4*k+3] = f.w;
        }
    }
    __syncthreads();

    // initial tv = logmap0(expmap0(v))
    DO_MAP();

    for (int s = 0; s < PRED; s++) {
        // ---- stage 1: h/g dual dot, u = silu(h)*sigmoid(g) ----
        {
            float h0 = 0.f, h1 = 0.f, g0 = 0.f, g1 = 0.f;
            const float4* wp = (const float4*)(sWhg + t * 68);
            #pragma unroll
            for (int k = 0; k < 16; k++) {
                float4 f = wp[k];
                h0 = fmaf(tv[2*k],     f.x, h0);
                g0 = fmaf(tv[2*k],     f.y, g0);
                h1 = fmaf(tv[2*k + 1], f.z, h1);
                g1 = fmaf(tv[2*k + 1], f.w, g1);
            }
            float h = (h0 + h1) + hb;
            float g = (g0 + g1) + gb;
            float sh = 1.0f / (1.0f + expf(-h));
            float sg = 1.0f / (1.0f + expf(-g));
            sU[t] = (h * sh) * sg;
        }
        __syncthreads();

        // ---- stage 2: wv partial (warp w covers j in [32w, 32w+32)) ----
        {
            float a0 = 0.f, a1 = 0.f, a2 = 0.f, a3 = 0.f;
            const float4* up = (const float4*)(sU + w * 32);
            const float4* wo = (const float4*)(sWo + lane * 68 + w * 32);
            #pragma unroll
            for (int k = 0; k < 8; k++) {
                float4 u4 = up[k];
                float4 w4 = wo[k];
                a0 = fmaf(u4.x, w4.x, a0);
                a1 = fmaf(u4.y, w4.y, a1);
                a2 = fmaf(u4.z, w4.z, a2);
                a3 = fmaf(u4.w, w4.w, a3);
            }
            sP[t] = (a0 + a1) + (a2 + a3);
        }
        __syncthreads();

        // ---- stage 3: vn = tv + (p0+p1) + bd_out  (replicated in all threads) ----
        {
            const float4* p0 = (const float4*)sP;
            const float4* p1 = (const float4*)(sP + 32);
            #pragma unroll
            for (int k = 0; k < 8; k++) {
                float4 a = p0[k];
                float4 c = p1[k];
                vn[4*k]   = (tv[4*k]   + (a.x + c.x)) + bdoV[4*k];
                vn[4*k+1] = (tv[4*k+1] + (a.y + c.y)) + bdoV[4*k+1];
                vn[4*k+2] = (tv[4*k+2] + (a.z + c.z)) + bdoV[4*k+2];
                vn[4*k+3] = (tv[4*k+3] + (a.w + c.w)) + bdoV[4*k+3];
            }
        }

        // ---- map: tv = logmap0(expmap0(vn)) ----
        DO_MAP();

        // ---- store tv (this is logmap0(zn) used by x_pred of step s) ----
        {
            float tm = 0.f;
            #pragma unroll
            for (int i = 0; i < 32; i++)
                if (lane == i) tm = tv[i];   // static-index select, stays in regs
            if (t < 32)
                g_tvn[(size_t)s * (BATCH * EDIM) + b * EDIM + t] = tm;
        }
    }
}

// ---------------------------------------------------------------------------
// Kernel C: preds[b,s,c] = tvn[s,b,:] @ Wr + br   (parallel over b,s-chunks)
// ---------------------------------------------------------------------------
__global__ void __launch_bounds__(128) kc_project(
    const float* __restrict__ Wr, const float* __restrict__ br,
    float* __restrict__ out)
{
    int b = blockIdx.x;
    int chunk = blockIdx.y;
    int c = threadIdx.x;

    __shared__ __align__(16) float sWt[128 * 36]; // Wr transposed, padded rows
    for (int idx = c; idx < EDIM * CH; idx += 128) {
        int i = idx >> 7, cc = idx & 127;         // Wr[i][cc]
        sWt[cc * 36 + i] = Wr[idx];
    }
    float brc = br[c];
    __syncthreads();

    float wrow[32];
    {
        const float4* wp = (const float4*)(sWt + c * 36);
        #pragma unroll
        for (int k = 0; k < 8; k++) {
            float4 f = wp[k];
            wrow[4*k] = f.x; wrow[4*k+1] = f.y; wrow[4*k+2] = f.z; wrow[4*k+3] = f.w;
        }
    }
    int sbeg = chunk * 56;
    for (int s = sbeg; s < sbeg + 56; s++) {
        const float4* tp = (const float4*)(g_tvn + (size_t)s * (BATCH * EDIM) + b * EDIM);
        float acc = 0.f;
        #pragma unroll
        for (int k = 0; k < 8; k++) {
            float4 f = tp[k];
            acc = fmaf(f.x, wrow[4*k],     acc);
            acc = fmaf(f.y, wrow[4*k + 1], acc);
            acc = fmaf(f.z, wrow[4*k + 2], acc);
            acc = fmaf(f.w, wrow[4*k + 3], acc);
        }
        out[((size_t)b * PRED + s) * CH + c] = acc + brc;
    }
}

// ---------------------------------------------------------------------------
extern "C" void kernel_launch(void* const* d_in, const int* in_sizes, int n_in,
                              void* d_out, int out_size)
{
    const float* x        = (const float*)d_in[0];
    const float* We_trend = (const float*)d_in[1];
    const float* be_trend = (const float*)d_in[2];
    const float* We_weekly= (const float*)d_in[3];
    const float* be_weekly= (const float*)d_in[4];
    const float* We_daily = (const float*)d_in[5];
    const float* be_daily = (const float*)d_in[6];
    const float* We_resid = (const float*)d_in[7];
    const float* be_resid = (const float*)d_in[8];
    const float* Wd_in    = (const float*)d_in[9];
    const float* bd_in    = (const float*)d_in[10];
    const float* Wd_gate  = (const float*)d_in[11];
    const float* bd_gate  = (const float*)d_in[12];
    const float* Wd_out   = (const float*)d_in[13];
    const float* bd_out   = (const float*)d_in[14];
    const float* Wr       = (const float*)d_in[15];
    const float* br       = (const float*)d_in[16];
    float* out = (float*)d_out;

    ka_encoder<<<BATCH, 256>>>(x, We_trend, be_trend, We_weekly, be_weekly,
                               We_daily, be_daily, We_resid, be_resid);
    kb_scan<<<BATCH, 64>>>(Wd_in, bd_in, Wd_gate, bd_gate, Wd_out, bd_out);
    kc_project<<<dim3(BATCH, 6), 128>>>(Wr, br, out);
}

// round 7
// speedup vs baseline: 1.6341x; 1.6341x over previous
#include <cuda_runtime.h>
#include <cuda_bf16.h>
#include <math.h>

#define EPSF 1e-6f
#define BATCH 128
#define TLEN  2048
#define CH    128
#define EDIM  32
#define HDIM  64
#define PRED  336

// scratch (allocation-free rule: __device__ globals)
__device__ __align__(16) float g_v[BATCH * EDIM];              // 16 KB
__device__ __align__(16) float g_tvn[PRED * BATCH * EDIM];     // 5.5 MB

// ---------------------------------------------------------------------------
// Kernel A: per-row moving-average decomposition + 4 GEMVs + tanh -> v[128,32]
// 4 independent accumulators + unroll -> ~32 loads in flight (was MLP~1).
// ---------------------------------------------------------------------------
__global__ void __launch_bounds__(256) ka_encoder(
    const float* __restrict__ x,
    const float* __restrict__ Wt, const float* __restrict__ bt,
    const float* __restrict__ Ww, const float* __restrict__ bw,
    const float* __restrict__ Wdm, const float* __restrict__ bdm,
    const float* __restrict__ Wre, const float* __restrict__ bre)
{
    int b = blockIdx.x;
    int tid = threadIdx.x;
    __shared__ float s0[TLEN];   // x[:,:,0] then residual
    __shared__ float st[TLEN];   // trend
    __shared__ float part[256];
    __shared__ float acc4[4][EDIM];

    const float* xb = x + (size_t)b * TLEN * CH;
    for (int t = tid; t < TLEN; t += 256) s0[t] = xb[(size_t)t * CH];
    __syncthreads();
    for (int t = tid; t < TLEN; t += 256) {
        float s = 0.f;
        #pragma unroll
        for (int d = -3; d <= 3; d++) {
            int u = t + d; u = min(max(u, 0), TLEN - 1);
            s += s0[u];
        }
        st[t] = s / 7.0f;
    }
    __syncthreads();
    for (int t = tid; t < TLEN; t += 256) s0[t] = s0[t] - st[t]; // residual
    __syncthreads();

    int combo = tid & 127;
    int e = combo & 31;
    int m = combo >> 5;         // 0: trend, 1: weekly, 2: daily, 3: resid
    int half = tid >> 7;
    const float* W = (m == 0) ? Wt : (m == 1) ? Ww : (m == 2) ? Wdm : Wre;
    const float* sig = (m == 0) ? st : s0;
    const float* Wp = W + e;
    int tbeg = half * (TLEN / 2);

    float a0 = 0.f, a1 = 0.f, a2 = 0.f, a3 = 0.f;
    #pragma unroll 8
    for (int t = tbeg; t < tbeg + TLEN / 2; t += 4) {
        a0 = fmaf(sig[t + 0], Wp[(t + 0) * EDIM], a0);
        a1 = fmaf(sig[t + 1], Wp[(t + 1) * EDIM], a1);
        a2 = fmaf(sig[t + 2], Wp[(t + 2) * EDIM], a2);
        a3 = fmaf(sig[t + 3], Wp[(t + 3) * EDIM], a3);
    }
    part[tid] = (a0 + a1) + (a2 + a3);
    __syncthreads();
    if (tid < 128) {
        float d = part[tid] + part[tid + 128];
        const float* be = (m == 0) ? bt : (m == 1) ? bw : (m == 2) ? bdm : bre;
        acc4[m][e] = tanhf(d + be[e]);
    }
    __syncthreads();
    if (tid < EDIM)
        g_v[b * EDIM + tid] = ((acc4[0][tid] + acc4[1][tid]) + acc4[2][tid]) + acc4[3][tid];
}

// ---------------------------------------------------------------------------
// Kernel B: 336-step serial scan, one 64-thread block per batch row.
// KEY: logmap0(expmap0(v)) == v identically, so the hyperbolic maps vanish:
//      tv_{s+1} = tv_s + MLP(tv_s),  x_pred_s = tv_{s+1} @ Wr + br.
// State lives in sTv[32]; 32 low threads update it (3 adds), everyone reloads
// via broadcast LDS.128. No norms, no cosh/sinh/acosh, no SEL-extraction.
// ---------------------------------------------------------------------------
__global__ void __launch_bounds__(64) kb_scan(
    const float* __restrict__ Wd_in, const float* __restrict__ bd_in,
    const float* __restrict__ Wd_gate, const float* __restrict__ bd_gate,
    const float* __restrict__ Wd_out, const float* __restrict__ bd_out)
{
    int b = blockIdx.x;
    int t = threadIdx.x;
    int lane = t & 31;
    int w = t >> 5;

    // padded shared layouts (row stride 68 floats = 272B -> conflict-free LDS.128)
    __shared__ __align__(16) float sWhg[64 * 68]; // [h-col t][pair(Win, Wgate) over i]
    __shared__ __align__(16) float sWo[32 * 68];  // [e-row i][j over 64]
    __shared__ __align__(16) float sU[64];
    __shared__ __align__(16) float sP[64];        // two wv partials
    __shared__ __align__(16) float sTv[EDIM];     // current tangent state

    for (int idx = t; idx < EDIM * HDIM; idx += 64) {
        int i = idx >> 6, c = idx & 63;          // Wd_in[i][c], i<32, c<64
        sWhg[c * 68 + 2 * i]     = Wd_in[idx];
        sWhg[c * 68 + 2 * i + 1] = Wd_gate[idx];
    }
    for (int idx = t; idx < HDIM * EDIM; idx += 64) {
        int j = idx >> 5, i = idx & 31;          // Wd_out[j][i]
        sWo[i * 68 + j] = Wd_out[idx];
    }
    float hb = bd_in[t];
    float gb = bd_gate[t];
    float bdo = (t < EDIM) ? bd_out[t] : 0.f;
    if (t < EDIM) sTv[t] = g_v[b * EDIM + t];    // tv_0 = logmap0(expmap0(v)) = v
    __syncthreads();

    float tv[32];
    #pragma unroll
    for (int k = 0; k < 8; k++) {
        float4 f = ((const float4*)sTv)[k];
        tv[4*k] = f.x; tv[4*k+1] = f.y; tv[4*k+2] = f.z; tv[4*k+3] = f.w;
    }

    float* outp = g_tvn + b * EDIM + t;          // valid use only when t < 32

    for (int s = 0; s < PRED; s++) {
        // ---- stage 1: h/g dual dot, u = silu(h)*sigmoid(g) ----
        {
            float h0 = 0.f, h1 = 0.f, g0 = 0.f, g1 = 0.f;
            const float4* wp = (const float4*)(sWhg + t * 68);
            #pragma unroll
            for (int k = 0; k < 16; k++) {
                float4 f = wp[k];
                h0 = fmaf(tv[2*k],     f.x, h0);
                g0 = fmaf(tv[2*k],     f.y, g0);
                h1 = fmaf(tv[2*k + 1], f.z, h1);
                g1 = fmaf(tv[2*k + 1], f.w, g1);
            }
            float h = (h0 + h1) + hb;
            float g = (g0 + g1) + gb;
            float sh = 1.0f / (1.0f + __expf(-h));
            float sg = 1.0f / (1.0f + __expf(-g));
            sU[t] = (h * sh) * sg;
        }
        __syncthreads();

        // ---- stage 2: wv partial (warp w covers j in [32w, 32w+32)) ----
        {
            float a0 = 0.f, a1 = 0.f, a2 = 0.f, a3 = 0.f;
            const float4* up = (const float4*)(sU + w * 32);   // broadcast
            const float4* wo = (const float4*)(sWo + lane * 68 + w * 32);
            #pragma unroll
            for (int k = 0; k < 8; k++) {
                float4 u4 = up[k];
                float4 w4 = wo[k];
                a0 = fmaf(u4.x, w4.x, a0);
                a1 = fmaf(u4.y, w4.y, a1);
                a2 = fmaf(u4.z, w4.z, a2);
                a3 = fmaf(u4.w, w4.w, a3);
            }
            sP[t] = (a0 + a1) + (a2 + a3);
        }
        __syncthreads();

        // ---- stage 3: tv_{s+1}[e] = tv_s[e] + p0 + p1 + bd_out[e]; store ----
        if (t < EDIM) {
            float nv = ((sTv[t] + (sP[t] + sP[t + 32])) + bdo);
            sTv[t] = nv;
            outp[(size_t)s * (BATCH * EDIM)] = nv;
        }
        __syncthreads();

        // ---- reload replicated state (broadcast LDS.128) ----
        #pragma unroll
        for (int k = 0; k < 8; k++) {
            float4 f = ((const float4*)sTv)[k];
            tv[4*k] = f.x; tv[4*k+1] = f.y; tv[4*k+2] = f.z; tv[4*k+3] = f.w;
        }
    }
}

// ---------------------------------------------------------------------------
// Kernel C: preds[b,s,c] = tvn[s,b,:] @ Wr + br   (parallel over b,s-chunks)
// ---------------------------------------------------------------------------
__global__ void __launch_bounds__(128) kc_project(
    const float* __restrict__ Wr, const float* __restrict__ br,
    float* __restrict__ out)
{
    int b = blockIdx.x;
    int chunk = blockIdx.y;
    int c = threadIdx.x;

    __shared__ __align__(16) float sWt[128 * 36]; // Wr transposed, padded rows
    for (int idx = c; idx < EDIM * CH; idx += 128) {
        int i = idx >> 7, cc = idx & 127;         // Wr[i][cc]
        sWt[cc * 36 + i] = Wr[idx];
    }
    float brc = br[c];
    __syncthreads();

    float wrow[32];
    {
        const float4* wp = (const float4*)(sWt + c * 36);
        #pragma unroll
        for (int k = 0; k < 8; k++) {
            float4 f = wp[k];
            wrow[4*k] = f.x; wrow[4*k+1] = f.y; wrow[4*k+2] = f.z; wrow[4*k+3] = f.w;
        }
    }
    int sbeg = chunk * 56;
    for (int s = sbeg; s < sbeg + 56; s++) {
        const float4* tp = (const float4*)(g_tvn + (size_t)s * (BATCH * EDIM) + b * EDIM);
        float acc = 0.f;
        #pragma unroll
        for (int k = 0; k < 8; k++) {
            float4 f = tp[k];
            acc = fmaf(f.x, wrow[4*k],     acc);
            acc = fmaf(f.y, wrow[4*k + 1], acc);
            acc = fmaf(f.z, wrow[4*k + 2], acc);
            acc = fmaf(f.w, wrow[4*k + 3], acc);
        }
        out[((size_t)b * PRED + s) * CH + c] = acc + brc;
    }
}

// ---------------------------------------------------------------------------
extern "C" void kernel_launch(void* const* d_in, const int* in_sizes, int n_in,
                              void* d_out, int out_size)
{
    const float* x        = (const float*)d_in[0];
    const float* We_trend = (const float*)d_in[1];
    const float* be_trend = (const float*)d_in[2];
    const float* We_weekly= (const float*)d_in[3];
    const float* be_weekly= (const float*)d_in[4];
    const float* We_daily = (const float*)d_in[5];
    const float* be_daily = (const float*)d_in[6];
    const float* We_resid = (const float*)d_in[7];
    const float* be_resid = (const float*)d_in[8];
    const float* Wd_in    = (const float*)d_in[9];
    const float* bd_in    = (const float*)d_in[10];
    const float* Wd_gate  = (const float*)d_in[11];
    const float* bd_gate  = (const float*)d_in[12];
    const float* Wd_out   = (const float*)d_in[13];
    const float* bd_out   = (const float*)d_in[14];
    const float* Wr       = (const float*)d_in[15];
    const float* br       = (const float*)d_in[16];
    float* out = (float*)d_out;

    ka_encoder<<<BATCH, 256>>>(x, We_trend, be_trend, We_weekly, be_weekly,
                               We_daily, be_daily, We_resid, be_resid);
    kb_scan<<<BATCH, 64>>>(Wd_in, bd_in, Wd_gate, bd_gate, Wd_out, bd_out);
    kc_project<<<dim3(BATCH, 6), 128>>>(Wr, br, out);
}

// round 8
// speedup vs baseline: 2.0581x; 1.2594x over previous
#include <cuda_runtime.h>
#include <cuda_bf16.h>
#include <math.h>

#define BATCH 128
#define TLEN  2048
#define CH    128
#define EDIM  32
#define HDIM  64
#define PRED  336

// scratch (allocation-free rule: __device__ globals)
__device__ __align__(16) float g_v[BATCH * EDIM];              // 16 KB
__device__ __align__(16) float g_tvn[PRED * BATCH * EDIM];     // 5.5 MB

// ---- packed f32x2 helpers (Blackwell) --------------------------------------
__device__ __forceinline__ void ffma2(unsigned long long& d,
                                      unsigned long long a,
                                      unsigned long long b) {
    asm("fma.rn.f32x2 %0, %1, %2, %0;" : "+l"(d) : "l"(a), "l"(b));
}
__device__ __forceinline__ float2 unpk(unsigned long long v) {
    float2 r; asm("mov.b64 {%0, %1}, %2;" : "=f"(r.x), "=f"(r.y) : "l"(v));
    return r;
}
__device__ __forceinline__ unsigned long long pk(float lo, float hi) {
    unsigned long long v;
    asm("mov.b64 %0, {%1, %2};" : "=l"(v) : "f"(lo), "f"(hi));
    return v;
}

// ---------------------------------------------------------------------------
// Kernel A: per-row moving-average decomposition + 4 GEMVs + tanh -> v[128,32]
// Explicit 32-deep load buffer forces MLP~32 (ptxas previously capped regs=32
// and left the GEMV at MLP~2 -> exposed L2 latency).
// ---------------------------------------------------------------------------
__global__ void __launch_bounds__(256, 1) ka_encoder(
    const float* __restrict__ x,
    const float* __restrict__ Wt, const float* __restrict__ bt,
    const float* __restrict__ Ww, const float* __restrict__ bw,
    const float* __restrict__ Wdm, const float* __restrict__ bdm,
    const float* __restrict__ Wre, const float* __restrict__ bre)
{
    int b = blockIdx.x;
    int tid = threadIdx.x;
    __shared__ float s0[TLEN];   // x[:,:,0] then residual
    __shared__ float st[TLEN];   // trend
    __shared__ float part[256];
    __shared__ float acc4[4][EDIM];

    const float* xb = x + (size_t)b * TLEN * CH;
    for (int t = tid; t < TLEN; t += 256) s0[t] = xb[(size_t)t * CH];
    __syncthreads();
    for (int t = tid; t < TLEN; t += 256) {
        float s = 0.f;
        #pragma unroll
        for (int d = -3; d <= 3; d++) {
            int u = t + d; u = min(max(u, 0), TLEN - 1);
            s += s0[u];
        }
        st[t] = s / 7.0f;
    }
    __syncthreads();
    for (int t = tid; t < TLEN; t += 256) s0[t] = s0[t] - st[t]; // residual
    __syncthreads();

    int combo = tid & 127;
    int e = combo & 31;
    int m = combo >> 5;         // 0: trend, 1: weekly, 2: daily, 3: resid
    int half = tid >> 7;
    const float* W = (m == 0) ? Wt : (m == 1) ? Ww : (m == 2) ? Wdm : Wre;
    const float* sig = (m == 0) ? st : s0;
    const float* Wp = W + e;
    int tbeg = half * (TLEN / 2);

    float a0 = 0.f, a1 = 0.f, a2 = 0.f, a3 = 0.f;
    for (int t = tbeg; t < tbeg + TLEN / 2; t += 32) {
        float wv[32];
        #pragma unroll
        for (int u = 0; u < 32; u++) wv[u] = Wp[(t + u) * EDIM];
        #pragma unroll
        for (int u = 0; u < 32; u += 4) {
            a0 = fmaf(sig[t + u + 0], wv[u + 0], a0);
            a1 = fmaf(sig[t + u + 1], wv[u + 1], a1);
            a2 = fmaf(sig[t + u + 2], wv[u + 2], a2);
            a3 = fmaf(sig[t + u + 3], wv[u + 3], a3);
        }
    }
    part[tid] = (a0 + a1) + (a2 + a3);
    __syncthreads();
    if (tid < 128) {
        float d = part[tid] + part[tid + 128];
        const float* be = (m == 0) ? bt : (m == 1) ? bw : (m == 2) ? bdm : bre;
        acc4[m][e] = tanhf(d + be[e]);
    }
    __syncthreads();
    if (tid < EDIM)
        g_v[b * EDIM + tid] = ((acc4[0][tid] + acc4[1][tid]) + acc4[2][tid]) + acc4[3][tid];
}

// ---------------------------------------------------------------------------
// Kernel B: 336-step serial scan, one 64-thread block per batch row.
// logmap0(expmap0(v)) == v identically -> tv_{s+1} = tv_s + MLP(tv_s).
// All weights live in registers (packed f32x2); stage1 = 32 FFMA2/thread,
// stage2 = 16 FFMA2 with (e = t>>1, half = t&1) split + shfl_xor combine.
// Only 2 barriers per step.
// ---------------------------------------------------------------------------
__global__ void __launch_bounds__(64) kb_scan(
    const float* __restrict__ Wd_in, const float* __restrict__ bd_in,
    const float* __restrict__ Wd_gate, const float* __restrict__ bd_gate,
    const float* __restrict__ Wd_out, const float* __restrict__ bd_out)
{
    int b = blockIdx.x;
    int t = threadIdx.x;        // 64 threads = 2 warps
    int e2 = t >> 1;            // output index for stage2/3 (0..31)
    int half = t & 1;           // which half of j-range this thread sums

    __shared__ __align__(16) float sU[HDIM];
    __shared__ __align__(16) float sTv[EDIM];

    // ---- load weights into registers (loop-invariant) ----
    unsigned long long whp[16], wgp[16], wop[16];
    #pragma unroll
    for (int k = 0; k < 16; k++) {
        whp[k] = pk(Wd_in [(2*k)*HDIM + t], Wd_in [(2*k+1)*HDIM + t]);
        wgp[k] = pk(Wd_gate[(2*k)*HDIM + t], Wd_gate[(2*k+1)*HDIM + t]);
    }
    {
        int j0 = half * 32;
        #pragma unroll
        for (int k = 0; k < 16; k++)
            wop[k] = pk(Wd_out[(j0 + 2*k)*EDIM + e2],
                        Wd_out[(j0 + 2*k + 1)*EDIM + e2]);
    }
    float hbias = bd_in[t];
    float gbias = bd_gate[t];
    float bdo   = bd_out[e2];

    if (t < EDIM) sTv[t] = g_v[b * EDIM + t];   // tv_0 = v
    __syncthreads();

    unsigned long long tvp[16];
    #pragma unroll
    for (int k = 0; k < 16; k++) tvp[k] = ((const unsigned long long*)sTv)[k];

    float* outp = g_tvn + b * EDIM + e2;

    for (int s = 0; s < PRED; s++) {
        // ---- stage 1: h_j, g_j for j = t; u = silu(h)*sigmoid(g) ----
        {
            unsigned long long hA = 0ull, hB = 0ull, gA = 0ull, gB = 0ull;
            #pragma unroll
            for (int k = 0; k < 8; k++) {
                ffma2(hA, tvp[2*k],     whp[2*k]);
                ffma2(hB, tvp[2*k + 1], whp[2*k + 1]);
                ffma2(gA, tvp[2*k],     wgp[2*k]);
                ffma2(gB, tvp[2*k + 1], wgp[2*k + 1]);
            }
            float2 u1 = unpk(hA), u2 = unpk(hB), u3 = unpk(gA), u4 = unpk(gB);
            float h = ((u1.x + u1.y) + (u2.x + u2.y)) + hbias;
            float g = ((u3.x + u3.y) + (u4.x + u4.y)) + gbias;
            float sh = 1.0f / (1.0f + __expf(-h));
            float sg = 1.0f / (1.0f + __expf(-g));
            sU[t] = (h * sh) * sg;
        }
        __syncthreads();

        // ---- stage 2: partial dot over this thread's half of j-range ----
        float p;
        {
            const unsigned long long* up =
                ((const unsigned long long*)sU) + half * 16;
            unsigned long long pA = 0ull, pB = 0ull;
            #pragma unroll
            for (int k = 0; k < 8; k++) {
                ffma2(pA, up[2*k],     wop[2*k]);
                ffma2(pB, up[2*k + 1], wop[2*k + 1]);
            }
            float2 q1 = unpk(pA), q2 = unpk(pB);
            p = (q1.x + q1.y) + (q2.x + q2.y);
        }
        p += __shfl_xor_sync(0xffffffffu, p, 1);   // combine halves (same warp)

        // ---- stage 3: even threads own e2; update state + store ----
        if (half == 0) {
            float nv = (sTv[e2] + p) + bdo;
            sTv[e2] = nv;
            outp[(size_t)s * (BATCH * EDIM)] = nv;
        }
        __syncthreads();

        // ---- reload replicated packed state (broadcast LDS) ----
        #pragma unroll
        for (int k = 0; k < 16; k++)
            tvp[k] = ((const unsigned long long*)sTv)[k];
    }
}

// ---------------------------------------------------------------------------
// Kernel C: preds[b,s,c] = tvn[s,b,:] @ Wr + br   (parallel over b,s-chunks)
// ---------------------------------------------------------------------------
__global__ void __launch_bounds__(128) kc_project(
    const float* __restrict__ Wr, const float* __restrict__ br,
    float* __restrict__ out)
{
    int b = blockIdx.x;
    int chunk = blockIdx.y;
    int c = threadIdx.x;

    __shared__ __align__(16) float sWt[128 * 36]; // Wr transposed, padded rows
    for (int idx = c; idx < EDIM * CH; idx += 128) {
        int i = idx >> 7, cc = idx & 127;         // Wr[i][cc]
        sWt[cc * 36 + i] = Wr[idx];
    }
    float brc = br[c];
    __syncthreads();

    float wrow[32];
    {
        const float4* wp = (const float4*)(sWt + c * 36);
        #pragma unroll
        for (int k = 0; k < 8; k++) {
            float4 f = wp[k];
            wrow[4*k] = f.x; wrow[4*k+1] = f.y; wrow[4*k+2] = f.z; wrow[4*k+3] = f.w;
        }
    }
    int sbeg = chunk * 56;
    for (int s = sbeg; s < sbeg + 56; s++) {
        const float4* tp = (const float4*)(g_tvn + (size_t)s * (BATCH * EDIM) + b * EDIM);
        float acc = 0.f;
        #pragma unroll
        for (int k = 0; k < 8; k++) {
            float4 f = tp[k];
            acc = fmaf(f.x, wrow[4*k],     acc);
            acc = fmaf(f.y, wrow[4*k + 1], acc);
            acc = fmaf(f.z, wrow[4*k + 2], acc);
            acc = fmaf(f.w, wrow[4*k + 3], acc);
        }
        out[((size_t)b * PRED + s) * CH + c] = acc + brc;
    }
}

// ---------------------------------------------------------------------------
extern "C" void kernel_launch(void* const* d_in, const int* in_sizes, int n_in,
                              void* d_out, int out_size)
{
    const float* x        = (const float*)d_in[0];
    const float* We_trend = (const float*)d_in[1];
    const float* be_trend = (const float*)d_in[2];
    const float* We_weekly= (const float*)d_in[3];
    const float* be_weekly= (const float*)d_in[4];
    const float* We_daily = (const float*)d_in[5];
    const float* be_daily = (const float*)d_in[6];
    const float* We_resid = (const float*)d_in[7];
    const float* be_resid = (const float*)d_in[8];
    const float* Wd_in    = (const float*)d_in[9];
    const float* bd_in    = (const float*)d_in[10];
    const float* Wd_gate  = (const float*)d_in[11];
    const float* bd_gate  = (const float*)d_in[12];
    const float* Wd_out   = (const float*)d_in[13];
    const float* bd_out   = (const float*)d_in[14];
    const float* Wr       = (const float*)d_in[15];
    const float* br       = (const float*)d_in[16];
    float* out = (float*)d_out;

    ka_encoder<<<BATCH, 256>>>(x, We_trend, be_trend, We_weekly, be_weekly,
                               We_daily, be_daily, We_resid, be_resid);
    kb_scan<<<BATCH, 64>>>(Wd_in, bd_in, Wd_gate, bd_gate, Wd_out, bd_out);
    kc_project<<<dim3(BATCH, 6), 128>>>(Wr, br, out);
}